// round 4
// baseline (speedup 1.0000x reference)
#include <cuda_runtime.h>
#include <cuda_fp16.h>

#define IN_DIM 128
#define OUT_DIM 32
#define NMAX 100000

__device__ __half g_zh[NMAX * OUT_DIM];    // z in fp16 (edge gather payload)
__device__ float g_el[NMAX];               // z @ a_l
__device__ float g_er[NMAX];               // z @ a_r
__device__ float g_esum[NMAX];             // sum exp(e) per dst
__device__ float g_hacc[NMAX * OUT_DIM];   // sum exp(e)*z[src] per dst (fp32)
__device__ float g_stats[2 * OUT_DIM];     // channel sum, sumsq

__device__ __forceinline__ void red_add_v4(float* addr, float4 v) {
    asm volatile("red.global.add.v4.f32 [%0], {%1,%2,%3,%4};"
                 :: "l"(addr), "f"(v.x), "f"(v.y), "f"(v.z), "f"(v.w)
                 : "memory");
}

// ---------------------------------------------------------------------------
// K0: zero accumulators (vectorized)
// ---------------------------------------------------------------------------
__global__ void k_zero(int n) {
    const int total4 = (n * OUT_DIM) / 4;
    const int stride = gridDim.x * blockDim.x;
    float4 z4 = make_float4(0.f, 0.f, 0.f, 0.f);
    float4* hacc4 = reinterpret_cast<float4*>(g_hacc);
    for (int i = blockIdx.x * blockDim.x + threadIdx.x; i < total4; i += stride) {
        hacc4[i] = z4;
        if (i < n) g_esum[i] = 0.0f;
        if (i < 2 * OUT_DIM) g_stats[i] = 0.0f;
    }
}

// ---------------------------------------------------------------------------
// K1: z = h @ W_fc (fp32 math, fp16 store) ; el = z@a_l ; er = z@a_r
// ---------------------------------------------------------------------------
__global__ void __launch_bounds__(256) k_gemm(
    const float* __restrict__ h, const float* __restrict__ Wfc,
    const float* __restrict__ Wa, int n)
{
    __shared__ float Ws[IN_DIM * OUT_DIM];        // 16 KB
    __shared__ float4 hs4[8][4 * 32];             // 16 KB

    for (int i = threadIdx.x; i < IN_DIM * OUT_DIM; i += blockDim.x)
        Ws[i] = Wfc[i];
    __syncthreads();

    const int lane = threadIdx.x & 31;
    const int wid  = threadIdx.x >> 5;
    const int gw   = (blockIdx.x * blockDim.x + threadIdx.x) >> 5;
    const int nw   = (gridDim.x * blockDim.x) >> 5;

    const float al = Wa[lane];
    const float ar = Wa[OUT_DIM + lane];
    float4* hsw = hs4[wid];

    const int ngroups = (n + 3) >> 2;
    for (int g = gw; g < ngroups; g += nw) {
        const int base = g * 4;
        #pragma unroll
        for (int i = 0; i < 4; i++) {
            int node = base + i;
            if (node < n)
                hsw[i * 32 + lane] =
                    reinterpret_cast<const float4*>(h + (size_t)node * IN_DIM)[lane];
        }
        __syncwarp();

        float acc0 = 0.f, acc1 = 0.f, acc2 = 0.f, acc3 = 0.f;
        #pragma unroll 8
        for (int k4 = 0; k4 < 32; k4++) {
            const float w0 = Ws[(k4 * 4 + 0) * 32 + lane];
            const float w1 = Ws[(k4 * 4 + 1) * 32 + lane];
            const float w2 = Ws[(k4 * 4 + 2) * 32 + lane];
            const float w3 = Ws[(k4 * 4 + 3) * 32 + lane];
            const float4 h0 = hsw[0 * 32 + k4];
            const float4 h1 = hsw[1 * 32 + k4];
            const float4 h2 = hsw[2 * 32 + k4];
            const float4 h3 = hsw[3 * 32 + k4];
            acc0 = fmaf(h0.x, w0, acc0); acc0 = fmaf(h0.y, w1, acc0);
            acc0 = fmaf(h0.z, w2, acc0); acc0 = fmaf(h0.w, w3, acc0);
            acc1 = fmaf(h1.x, w0, acc1); acc1 = fmaf(h1.y, w1, acc1);
            acc1 = fmaf(h1.z, w2, acc1); acc1 = fmaf(h1.w, w3, acc1);
            acc2 = fmaf(h2.x, w0, acc2); acc2 = fmaf(h2.y, w1, acc2);
            acc2 = fmaf(h2.z, w2, acc2); acc2 = fmaf(h2.w, w3, acc2);
            acc3 = fmaf(h3.x, w0, acc3); acc3 = fmaf(h3.y, w1, acc3);
            acc3 = fmaf(h3.z, w2, acc3); acc3 = fmaf(h3.w, w3, acc3);
        }

        float zz[4] = {acc0, acc1, acc2, acc3};
        #pragma unroll
        for (int i = 0; i < 4; i++) {
            int node = base + i;
            if (node >= n) break;
            float z = zz[i];
            g_zh[node * OUT_DIM + lane] = __float2half_rn(z);
            float vl = z * al;
            float vr = z * ar;
            #pragma unroll
            for (int off = 16; off; off >>= 1) {
                vl += __shfl_xor_sync(0xffffffffu, vl, off);
                vr += __shfl_xor_sync(0xffffffffu, vr, off);
            }
            if (lane == 0) { g_el[node] = vl; g_er[node] = vr; }
        }
        __syncwarp();
    }
}

// ---------------------------------------------------------------------------
// K2: edge pass, 8 edges per warp; 4 lanes per edge, each lane gathers
// 8 fp16 channels (16B) and emits 2 v4 fp32 REDs. Unnormalized softmax.
// ---------------------------------------------------------------------------
__global__ void __launch_bounds__(256) k_edges(
    const int* __restrict__ src, const int* __restrict__ dst, int nedges)
{
    const int lane = threadIdx.x & 31;
    const int sub  = lane >> 2;          // edge slot 0..7
    const int q    = lane & 3;           // 8-channel quarter
    const int gw   = (blockIdx.x * blockDim.x + threadIdx.x) >> 5;
    const int nw   = (gridDim.x * blockDim.x) >> 5;

    for (int base = gw * 8; base < nedges; base += nw * 8) {
        const int e = base + sub;
        if (e >= nedges) break;
        const int s = __ldg(&src[e]);
        const int d = __ldg(&dst[e]);
        float ee = __ldg(&g_el[s]) + __ldg(&g_er[d]);
        ee = (ee >= 0.0f) ? ee : 0.01f * ee;
        const float p = __expf(ee);
        if (q == 0) atomicAdd(&g_esum[d], p);

        const float4 raw = __ldg(reinterpret_cast<const float4*>(g_zh + s * OUT_DIM) + q);
        const __half2 ha = *reinterpret_cast<const __half2*>(&raw.x);
        const __half2 hb = *reinterpret_cast<const __half2*>(&raw.y);
        const __half2 hc = *reinterpret_cast<const __half2*>(&raw.z);
        const __half2 hd = *reinterpret_cast<const __half2*>(&raw.w);
        const float2 fa = __half22float2(ha);
        const float2 fb = __half22float2(hb);
        const float2 fc = __half22float2(hc);
        const float2 fd = __half22float2(hd);

        float* outp = g_hacc + d * OUT_DIM + q * 8;
        red_add_v4(outp,     make_float4(p * fa.x, p * fa.y, p * fb.x, p * fb.y));
        red_add_v4(outp + 4, make_float4(p * fc.x, p * fc.y, p * fd.x, p * fd.y));
    }
}

// ---------------------------------------------------------------------------
// K3: BN stats, float4 per thread (4 channels), per-thread rcp.
// ---------------------------------------------------------------------------
__global__ void __launch_bounds__(256) k_stats(int n)
{
    __shared__ float4 redbuf[2][8][8];           // [sum/sq][warp][quarter]
    const int lane = threadIdx.x & 31;
    const int wid  = threadIdx.x >> 5;
    const int q    = threadIdx.x & 7;            // channel quarter (fixed: stride%8==0)
    const int total4 = n * 8;                    // float4 elements
    const int stride = gridDim.x * blockDim.x;
    const float4* hacc4 = reinterpret_cast<const float4*>(g_hacc);

    float4 s  = make_float4(0.f, 0.f, 0.f, 0.f);
    float4 sq = make_float4(0.f, 0.f, 0.f, 0.f);
    for (int i = blockIdx.x * blockDim.x + threadIdx.x; i < total4; i += stride) {
        const int node = i >> 3;
        const float es = __ldg(&g_esum[node]);
        const float inv = (es > 0.0f) ? __frcp_rn(es) : 0.0f;
        float4 v = hacc4[i];
        v.x *= inv; v.y *= inv; v.z *= inv; v.w *= inv;
        s.x += v.x; s.y += v.y; s.z += v.z; s.w += v.w;
        sq.x = fmaf(v.x, v.x, sq.x); sq.y = fmaf(v.y, v.y, sq.y);
        sq.z = fmaf(v.z, v.z, sq.z); sq.w = fmaf(v.w, v.w, sq.w);
    }
    // fold the 4 warp-copies of each quarter (lanes q, q+8, q+16, q+24)
    #pragma unroll
    for (int off = 16; off >= 8; off >>= 1) {
        s.x += __shfl_xor_sync(0xffffffffu, s.x, off);
        s.y += __shfl_xor_sync(0xffffffffu, s.y, off);
        s.z += __shfl_xor_sync(0xffffffffu, s.z, off);
        s.w += __shfl_xor_sync(0xffffffffu, s.w, off);
        sq.x += __shfl_xor_sync(0xffffffffu, sq.x, off);
        sq.y += __shfl_xor_sync(0xffffffffu, sq.y, off);
        sq.z += __shfl_xor_sync(0xffffffffu, sq.z, off);
        sq.w += __shfl_xor_sync(0xffffffffu, sq.w, off);
    }
    if (lane < 8) { redbuf[0][wid][lane] = s; redbuf[1][wid][lane] = sq; }
    __syncthreads();
    if (wid == 0 && lane < 8) {
        float4 a = make_float4(0.f, 0.f, 0.f, 0.f);
        float4 b = make_float4(0.f, 0.f, 0.f, 0.f);
        #pragma unroll
        for (int w = 0; w < 8; w++) {
            float4 t = redbuf[0][w][lane];
            a.x += t.x; a.y += t.y; a.z += t.z; a.w += t.w;
            t = redbuf[1][w][lane];
            b.x += t.x; b.y += t.y; b.z += t.z; b.w += t.w;
        }
        atomicAdd(&g_stats[lane * 4 + 0], a.x);
        atomicAdd(&g_stats[lane * 4 + 1], a.y);
        atomicAdd(&g_stats[lane * 4 + 2], a.z);
        atomicAdd(&g_stats[lane * 4 + 3], a.w);
        atomicAdd(&g_stats[OUT_DIM + lane * 4 + 0], b.x);
        atomicAdd(&g_stats[OUT_DIM + lane * 4 + 1], b.y);
        atomicAdd(&g_stats[OUT_DIM + lane * 4 + 2], b.z);
        atomicAdd(&g_stats[OUT_DIM + lane * 4 + 3], b.w);
    }
}

// ---------------------------------------------------------------------------
// K4: normalize + BN affine + ELU, float4 per thread, single out write.
// ---------------------------------------------------------------------------
__global__ void __launch_bounds__(256) k_elu(float* __restrict__ out,
                                             const float* __restrict__ gamma,
                                             const float* __restrict__ beta, int n)
{
    __shared__ float sc_s[OUT_DIM], sh_s[OUT_DIM];
    if (threadIdx.x < OUT_DIM) {
        const int t = threadIdx.x;
        const float inv_n = 1.0f / (float)n;
        const float mean = g_stats[t] * inv_n;
        const float var  = g_stats[OUT_DIM + t] * inv_n - mean * mean;
        const float sc   = gamma[t] * rsqrtf(var + 1e-5f);
        sc_s[t] = sc;
        sh_s[t] = beta[t] - mean * sc;
    }
    __syncthreads();

    const int q = threadIdx.x & 7;
    const float4 sc = reinterpret_cast<const float4*>(sc_s)[q];
    const float4 sh = reinterpret_cast<const float4*>(sh_s)[q];
    const int total4 = n * 8;
    const int stride = gridDim.x * blockDim.x;
    const float4* hacc4 = reinterpret_cast<const float4*>(g_hacc);
    float4* out4 = reinterpret_cast<float4*>(out);

    for (int i = blockIdx.x * blockDim.x + threadIdx.x; i < total4; i += stride) {
        const int node = i >> 3;
        const float es = __ldg(&g_esum[node]);
        const float inv = (es > 0.0f) ? __frcp_rn(es) : 0.0f;
        float4 v = hacc4[i];
        v.x = fmaf(v.x * inv, sc.x, sh.x);
        v.y = fmaf(v.y * inv, sc.y, sh.y);
        v.z = fmaf(v.z * inv, sc.z, sh.z);
        v.w = fmaf(v.w * inv, sc.w, sh.w);
        v.x = (v.x > 0.f) ? v.x : expm1f(v.x);
        v.y = (v.y > 0.f) ? v.y : expm1f(v.y);
        v.z = (v.z > 0.f) ? v.z : expm1f(v.z);
        v.w = (v.w > 0.f) ? v.w : expm1f(v.w);
        out4[i] = v;
    }
}

// ---------------------------------------------------------------------------
extern "C" void kernel_launch(void* const* d_in, const int* in_sizes, int n_in,
                              void* d_out, int out_size)
{
    const float* h     = (const float*)d_in[0];
    const float* Wfc   = (const float*)d_in[1];
    const float* Wa    = (const float*)d_in[2];
    const float* gamma = (const float*)d_in[3];
    const float* beta  = (const float*)d_in[4];
    const int*   src   = (const int*)d_in[5];
    const int*   dst   = (const int*)d_in[6];

    const int n      = in_sizes[0] / IN_DIM;   // 100000
    const int nedges = in_sizes[5];            // 1600000
    float* out = (float*)d_out;

    k_zero <<<1024, 256>>>(n);
    k_gemm <<<1480, 256>>>(h, Wfc, Wa, n);
    k_edges<<<4096, 256>>>(src, dst, nedges);
    k_stats<<<1024, 256>>>(n);
    k_elu  <<<1024, 256>>>(out, gamma, beta, n);
}

// round 5
// speedup vs baseline: 1.2474x; 1.2474x over previous
#include <cuda_runtime.h>

#define IN_DIM 128
#define OUT_DIM 32
#define NMAX 100000

__device__ float g_z[NMAX * OUT_DIM];      // z = h @ W_fc
__device__ float g_el[NMAX];               // z @ a_l
__device__ float g_er[NMAX];               // z @ a_r
__device__ float g_esum[NMAX];             // sum exp(e) per dst
__device__ float g_hacc[NMAX * OUT_DIM];   // sum exp(e)*z[src] per dst
__device__ float g_stats[2 * OUT_DIM];     // channel sum, sumsq

__device__ __forceinline__ void red_add_v4(float* addr, float4 v) {
    asm volatile("red.global.add.v4.f32 [%0], {%1,%2,%3,%4};"
                 :: "l"(addr), "f"(v.x), "f"(v.y), "f"(v.z), "f"(v.w)
                 : "memory");
}

// ---------------------------------------------------------------------------
// K1: zero accumulators (store pipe is idle during GEMM -> near-free),
// then z = h @ W_fc ; el = z@a_l ; er = z@a_r   (warp: 4 nodes, lane = col)
// ---------------------------------------------------------------------------
__global__ void __launch_bounds__(256) k_gemm(
    const float* __restrict__ h, const float* __restrict__ Wfc,
    const float* __restrict__ Wa, int n)
{
    __shared__ float Ws[IN_DIM * OUT_DIM];        // 16 KB
    __shared__ float4 hs4[8][4 * 32];             // 16 KB

    // -- integrated zeroing (completes before kernel end; k_edges is stream-ordered after)
    {
        const int tid = blockIdx.x * blockDim.x + threadIdx.x;
        const int gs  = gridDim.x * blockDim.x;
        float4 z4 = make_float4(0.f, 0.f, 0.f, 0.f);
        float4* hacc4 = reinterpret_cast<float4*>(g_hacc);
        const int total4 = n * (OUT_DIM / 4);
        for (int i = tid; i < total4; i += gs) hacc4[i] = z4;
        for (int i = tid; i < n; i += gs) g_esum[i] = 0.0f;
        if (tid < 2 * OUT_DIM) g_stats[tid] = 0.0f;
    }

    for (int i = threadIdx.x; i < IN_DIM * OUT_DIM; i += blockDim.x)
        Ws[i] = Wfc[i];
    __syncthreads();

    const int lane = threadIdx.x & 31;
    const int wid  = threadIdx.x >> 5;
    const int gw   = (blockIdx.x * blockDim.x + threadIdx.x) >> 5;
    const int nw   = (gridDim.x * blockDim.x) >> 5;

    const float al = Wa[lane];
    const float ar = Wa[OUT_DIM + lane];
    float4* hsw = hs4[wid];

    const int ngroups = (n + 3) >> 2;
    for (int g = gw; g < ngroups; g += nw) {
        const int base = g * 4;
        #pragma unroll
        for (int i = 0; i < 4; i++) {
            int node = base + i;
            if (node < n)
                hsw[i * 32 + lane] =
                    reinterpret_cast<const float4*>(h + (size_t)node * IN_DIM)[lane];
        }
        __syncwarp();

        float acc0 = 0.f, acc1 = 0.f, acc2 = 0.f, acc3 = 0.f;
        #pragma unroll 8
        for (int k4 = 0; k4 < 32; k4++) {
            const float w0 = Ws[(k4 * 4 + 0) * 32 + lane];
            const float w1 = Ws[(k4 * 4 + 1) * 32 + lane];
            const float w2 = Ws[(k4 * 4 + 2) * 32 + lane];
            const float w3 = Ws[(k4 * 4 + 3) * 32 + lane];
            const float4 h0 = hsw[0 * 32 + k4];
            const float4 h1 = hsw[1 * 32 + k4];
            const float4 h2 = hsw[2 * 32 + k4];
            const float4 h3 = hsw[3 * 32 + k4];
            acc0 = fmaf(h0.x, w0, acc0); acc0 = fmaf(h0.y, w1, acc0);
            acc0 = fmaf(h0.z, w2, acc0); acc0 = fmaf(h0.w, w3, acc0);
            acc1 = fmaf(h1.x, w0, acc1); acc1 = fmaf(h1.y, w1, acc1);
            acc1 = fmaf(h1.z, w2, acc1); acc1 = fmaf(h1.w, w3, acc1);
            acc2 = fmaf(h2.x, w0, acc2); acc2 = fmaf(h2.y, w1, acc2);
            acc2 = fmaf(h2.z, w2, acc2); acc2 = fmaf(h2.w, w3, acc2);
            acc3 = fmaf(h3.x, w0, acc3); acc3 = fmaf(h3.y, w1, acc3);
            acc3 = fmaf(h3.z, w2, acc3); acc3 = fmaf(h3.w, w3, acc3);
        }

        float zz[4] = {acc0, acc1, acc2, acc3};
        #pragma unroll
        for (int i = 0; i < 4; i++) {
            int node = base + i;
            if (node >= n) break;
            float z = zz[i];
            g_z[node * OUT_DIM + lane] = z;
            float vl = z * al;
            float vr = z * ar;
            #pragma unroll
            for (int off = 16; off; off >>= 1) {
                vl += __shfl_xor_sync(0xffffffffu, vl, off);
                vr += __shfl_xor_sync(0xffffffffu, vr, off);
            }
            if (lane == 0) { g_el[node] = vl; g_er[node] = vr; }
        }
        __syncwarp();
    }
}

// ---------------------------------------------------------------------------
// K2: edge pass, 8 edges per warp (2 per lane-group, interleaved for MLP).
// 8 lanes per edge, each lane owns a float4 quarter of the channel row.
// Unnormalized softmax accumulation (shift-invariance; |e| small).
// ---------------------------------------------------------------------------
__global__ void __launch_bounds__(256) k_edges(
    const int* __restrict__ src, const int* __restrict__ dst, int nedges)
{
    const int lane = threadIdx.x & 31;
    const int sub  = lane >> 3;          // edge slot 0..3
    const int q    = lane & 7;           // float4 quarter
    const int gw   = (blockIdx.x * blockDim.x + threadIdx.x) >> 5;
    const int nw   = (gridDim.x * blockDim.x) >> 5;

    for (int base = gw * 8; base < nedges; base += nw * 8) {
        const int e0 = base + sub;
        const int e1 = base + 4 + sub;
        const bool v0 = e0 < nedges;
        const bool v1 = e1 < nedges;

        int s0 = 0, d0 = 0, s1 = 0, d1 = 0;
        if (v0) { s0 = __ldg(&src[e0]); d0 = __ldg(&dst[e0]); }
        if (v1) { s1 = __ldg(&src[e1]); d1 = __ldg(&dst[e1]); }

        float ee0 = 0.f, ee1 = 0.f;
        if (v0) ee0 = __ldg(&g_el[s0]) + __ldg(&g_er[d0]);
        if (v1) ee1 = __ldg(&g_el[s1]) + __ldg(&g_er[d1]);
        ee0 = (ee0 >= 0.0f) ? ee0 : 0.01f * ee0;
        ee1 = (ee1 >= 0.0f) ? ee1 : 0.01f * ee1;
        const float p0 = __expf(ee0);
        const float p1 = __expf(ee1);

        float4 zv0, zv1;
        if (v0) zv0 = __ldg(reinterpret_cast<const float4*>(g_z + s0 * OUT_DIM) + q);
        if (v1) zv1 = __ldg(reinterpret_cast<const float4*>(g_z + s1 * OUT_DIM) + q);

        if (v0) {
            if (q == 0) atomicAdd(&g_esum[d0], p0);
            red_add_v4(g_hacc + d0 * OUT_DIM + q * 4,
                       make_float4(p0 * zv0.x, p0 * zv0.y, p0 * zv0.z, p0 * zv0.w));
        }
        if (v1) {
            if (q == 0) atomicAdd(&g_esum[d1], p1);
            red_add_v4(g_hacc + d1 * OUT_DIM + q * 4,
                       make_float4(p1 * zv1.x, p1 * zv1.y, p1 * zv1.z, p1 * zv1.w));
        }
    }
}

// ---------------------------------------------------------------------------
// K3: BN stats, warp-per-node, 2 independent node chains per iteration (ILP).
// ---------------------------------------------------------------------------
__global__ void __launch_bounds__(256) k_stats(int n)
{
    __shared__ float redbuf[2][8][32];
    const int lane = threadIdx.x & 31;
    const int wid  = threadIdx.x >> 5;
    const int gw   = (blockIdx.x * blockDim.x + threadIdx.x) >> 5;
    const int nw   = (gridDim.x * blockDim.x) >> 5;

    float s = 0.f, sq = 0.f;
    for (int nd = gw; nd < n; nd += 2 * nw) {
        const int n0 = nd;
        const int n1 = nd + nw;
        const bool v1 = n1 < n;
        // issue both hacc loads + both esum loads before consuming
        const float a0 = g_hacc[n0 * OUT_DIM + lane];
        const float a1 = v1 ? g_hacc[n1 * OUT_DIM + lane] : 0.0f;
        float inv0 = 0.f, inv1 = 0.f;
        if (lane == 0) {
            const float e0 = g_esum[n0];
            const float e1 = v1 ? g_esum[n1] : 0.0f;
            inv0 = (e0 > 0.0f) ? __frcp_rn(e0) : 0.0f;
            inv1 = (e1 > 0.0f) ? __frcp_rn(e1) : 0.0f;
        }
        inv0 = __shfl_sync(0xffffffffu, inv0, 0);
        inv1 = __shfl_sync(0xffffffffu, inv1, 0);
        const float x0 = a0 * inv0;
        const float x1 = a1 * inv1;
        s += x0 + x1;
        sq = fmaf(x0, x0, sq);
        sq = fmaf(x1, x1, sq);
    }
    redbuf[0][wid][lane] = s;
    redbuf[1][wid][lane] = sq;
    __syncthreads();
    if (wid == 0) {
        float a = 0.f, b = 0.f;
        #pragma unroll
        for (int w = 0; w < 8; w++) { a += redbuf[0][w][lane]; b += redbuf[1][w][lane]; }
        atomicAdd(&g_stats[lane], a);
        atomicAdd(&g_stats[OUT_DIM + lane], b);
    }
}

// ---------------------------------------------------------------------------
// K4: normalize + BN affine + ELU; warp-per-node, 2 node chains per iter.
// ---------------------------------------------------------------------------
__global__ void __launch_bounds__(256) k_elu(float* __restrict__ out,
                                             const float* __restrict__ gamma,
                                             const float* __restrict__ beta, int n)
{
    __shared__ float sc_s[OUT_DIM], sh_s[OUT_DIM];
    if (threadIdx.x < OUT_DIM) {
        const int t = threadIdx.x;
        const float inv_n = 1.0f / (float)n;
        const float mean = g_stats[t] * inv_n;
        const float var  = g_stats[OUT_DIM + t] * inv_n - mean * mean;
        const float sc   = gamma[t] * rsqrtf(var + 1e-5f);
        sc_s[t] = sc;
        sh_s[t] = beta[t] - mean * sc;
    }
    __syncthreads();

    const int lane = threadIdx.x & 31;
    const int gw   = (blockIdx.x * blockDim.x + threadIdx.x) >> 5;
    const int nw   = (gridDim.x * blockDim.x) >> 5;
    const float sc = sc_s[lane];
    const float sh = sh_s[lane];

    for (int nd = gw; nd < n; nd += 2 * nw) {
        const int n0 = nd;
        const int n1 = nd + nw;
        const bool v1 = n1 < n;
        const float a0 = g_hacc[n0 * OUT_DIM + lane];
        const float a1 = v1 ? g_hacc[n1 * OUT_DIM + lane] : 0.0f;
        float inv0 = 0.f, inv1 = 0.f;
        if (lane == 0) {
            const float e0 = g_esum[n0];
            const float e1 = v1 ? g_esum[n1] : 0.0f;
            inv0 = (e0 > 0.0f) ? __frcp_rn(e0) : 0.0f;
            inv1 = (e1 > 0.0f) ? __frcp_rn(e1) : 0.0f;
        }
        inv0 = __shfl_sync(0xffffffffu, inv0, 0);
        inv1 = __shfl_sync(0xffffffffu, inv1, 0);
        float x0 = fmaf(a0 * inv0, sc, sh);
        x0 = (x0 > 0.0f) ? x0 : expm1f(x0);
        out[n0 * OUT_DIM + lane] = x0;
        if (v1) {
            float x1 = fmaf(a1 * inv1, sc, sh);
            x1 = (x1 > 0.0f) ? x1 : expm1f(x1);
            out[n1 * OUT_DIM + lane] = x1;
        }
    }
}

// ---------------------------------------------------------------------------
extern "C" void kernel_launch(void* const* d_in, const int* in_sizes, int n_in,
                              void* d_out, int out_size)
{
    const float* h     = (const float*)d_in[0];
    const float* Wfc   = (const float*)d_in[1];
    const float* Wa    = (const float*)d_in[2];
    const float* gamma = (const float*)d_in[3];
    const float* beta  = (const float*)d_in[4];
    const int*   src   = (const int*)d_in[5];
    const int*   dst   = (const int*)d_in[6];

    const int n      = in_sizes[0] / IN_DIM;   // 100000
    const int nedges = in_sizes[5];            // 1600000
    float* out = (float*)d_out;

    k_gemm <<<1480, 256>>>(h, Wfc, Wa, n);
    k_edges<<<4096, 256>>>(src, dst, nedges);
    k_stats<<<1024, 256>>>(n);
    k_elu  <<<1024, 256>>>(out, gamma, beta, n);
}